// round 5
// baseline (speedup 1.0000x reference)
#include <cuda_runtime.h>
#include <cuda_bf16.h>
#include <cstdint>

#define NS0 300000
#define ND0 50000
#define NE0 800000
#define NS1 50000
#define ND1 8192
#define NE1 131072
#define INF 256
#define HIDF 128
#define OUTF 128

// ---------------- static device scratch ----------------
__device__ int   g_deg_out0[NS0];
__device__ int   g_deg_in0[ND0];
__device__ int   g_rowptr0[ND0 + 1];
__device__ int   g_work0[ND0];        // atomically-bumped rowptr copy
__device__ int2  g_csr0[NE0];         // packed (src, w bits)
__device__ float g_h1[(size_t)ND0 * HIDF];     // 25.6 MB

__device__ int   g_deg_out1[NS1];
__device__ int   g_deg_in1[ND1];
__device__ int   g_rowptr1[ND1 + 1];
__device__ int   g_work1[ND1];
__device__ int2  g_csr1[NE1];

// ---------------- helpers ----------------
__device__ __forceinline__ uint32_t f2tf32(float f) {
    uint32_t r;
    asm("cvt.rna.tf32.f32 %0, %1;" : "=r"(r) : "f"(f));
    return r;
}

__device__ __forceinline__ void mma_tf32(float d[4], const uint32_t a[4],
                                         const uint32_t b0, const uint32_t b1,
                                         const float c[4]) {
    asm volatile(
        "mma.sync.aligned.m16n8k8.row.col.f32.tf32.tf32.f32 "
        "{%0,%1,%2,%3}, {%4,%5,%6,%7}, {%8,%9}, {%10,%11,%12,%13};\n"
        : "=f"(d[0]), "=f"(d[1]), "=f"(d[2]), "=f"(d[3])
        : "r"(a[0]), "r"(a[1]), "r"(a[2]), "r"(a[3]),
          "r"(b0), "r"(b1),
          "f"(c[0]), "f"(c[1]), "f"(c[2]), "f"(c[3]));
}

// ---------------- preprocessing ----------------

// 2 edges per thread via int2 loads -> 400k threads.
__global__ void __launch_bounds__(256) k_degree(const int* __restrict__ src0,
                                                const int* __restrict__ dst0,
                                                const int* __restrict__ src1,
                                                const int* __restrict__ dst1) {
    int i = blockIdx.x * blockDim.x + threadIdx.x;
    if (i < NE0 / 2) {
        int2 s = ((const int2*)src0)[i];
        int2 d = ((const int2*)dst0)[i];
        atomicAdd(&g_deg_out0[s.x], 1); atomicAdd(&g_deg_out0[s.y], 1);
        atomicAdd(&g_deg_in0[d.x], 1);  atomicAdd(&g_deg_in0[d.y], 1);
    }
    if (i < NE1 / 2) {
        int2 s = ((const int2*)src1)[i];
        int2 d = ((const int2*)dst1)[i];
        atomicAdd(&g_deg_out1[s.x], 1); atomicAdd(&g_deg_out1[s.y], 1);
        atomicAdd(&g_deg_in1[d.x], 1);  atomicAdd(&g_deg_in1[d.y], 1);
    }
}

// Exclusive scan; writes rowptr AND a working copy for the fill pass.
__device__ __forceinline__ void scan_body(const int* __restrict__ deg,
                                          int* __restrict__ rowptr,
                                          int* __restrict__ work, int n) {
    __shared__ int partial[1024];
    const int t = threadIdx.x;
    const int C = (n + 1023) / 1024;
    const int start = t * C;
    const int end = min(start + C, n);
    int s = 0;
    for (int i = start; i < end; i++) s += deg[i];
    partial[t] = s;
    __syncthreads();
    for (int off = 1; off < 1024; off <<= 1) {
        int v = partial[t];
        int add = (t >= off) ? partial[t - off] : 0;
        __syncthreads();
        partial[t] = v + add;
        __syncthreads();
    }
    int run = (t == 0) ? 0 : partial[t - 1];
    for (int i = start; i < end; i++) {
        rowptr[i] = run;
        work[i] = run;
        run += deg[i];
    }
    if (t == 0) rowptr[n] = partial[1023];
}

__global__ void k_scan_both() {
    if (blockIdx.x == 0) scan_body(g_deg_in0, g_rowptr0, g_work0, ND0);
    else                 scan_body(g_deg_in1, g_rowptr1, g_work1, ND1);
}

// 2 edges per thread; atomic bump directly on the rowptr working copy;
// packed (src, weight) 8-byte store.
__global__ void __launch_bounds__(256) k_fill(const int* __restrict__ src0,
                                              const int* __restrict__ dst0,
                                              const float* __restrict__ ew0,
                                              const int* __restrict__ src1,
                                              const int* __restrict__ dst1,
                                              const float* __restrict__ ew1) {
    int i = blockIdx.x * blockDim.x + threadIdx.x;
    if (i < NE0 / 2) {
        int2   s = ((const int2*)src0)[i];
        int2   d = ((const int2*)dst0)[i];
        float2 w = ((const float2*)ew0)[i];
        int pos0 = atomicAdd(&g_work0[d.x], 1);
        int pos1 = atomicAdd(&g_work0[d.y], 1);
        float w0 = w.x * rsqrtf(fmaxf((float)g_deg_out0[s.x], 1.0f));
        float w1 = w.y * rsqrtf(fmaxf((float)g_deg_out0[s.y], 1.0f));
        g_csr0[pos0] = make_int2(s.x, __float_as_int(w0));
        g_csr0[pos1] = make_int2(s.y, __float_as_int(w1));
    }
    if (i < NE1 / 2) {
        int2   s = ((const int2*)src1)[i];
        int2   d = ((const int2*)dst1)[i];
        float2 w = ((const float2*)ew1)[i];
        int pos0 = atomicAdd(&g_work1[d.x], 1);
        int pos1 = atomicAdd(&g_work1[d.y], 1);
        float w0 = w.x * rsqrtf(fmaxf((float)g_deg_out1[s.x], 1.0f));
        float w1 = w.y * rsqrtf(fmaxf((float)g_deg_out1[s.y], 1.0f));
        g_csr1[pos0] = make_int2(s.x, __float_as_int(w0));
        g_csr1[pos1] = make_int2(s.y, __float_as_int(w1));
    }
}

// ---------------- fused aggregate + TF32 GEMM ----------------
// Per block (512 threads): gather 64 dst rows (D feats each) into smem,
// then compute relu(A[64,D] @ W[D,128] + bias) with tensor cores.
// 16 warps: 4 along M (16 rows each) x 4 along N (32 cols each).
template <int D>
__global__ void __launch_bounds__(512) k_fused(const int* __restrict__ rowptr,
                                               const int2* __restrict__ csr,
                                               const float* __restrict__ feat,
                                               const int* __restrict__ indeg,
                                               const float* __restrict__ W,
                                               const float* __restrict__ bias,
                                               float* __restrict__ out,
                                               int nrows) {
    constexpr int ASTRIDE = D + 4;
    constexpr int TPR = D / 4;           // threads per row (float4 each)
    constexpr int ROWS_PAR = 512 / TPR;  // rows gathered in parallel
    extern __shared__ char smem_raw[];
    float*    Ash = (float*)smem_raw;                          // 64*ASTRIDE floats
    uint32_t* Wsh = (uint32_t*)(smem_raw + 64 * ASTRIDE * 4);  // 32*136 u32

    const int tid = threadIdx.x;
    const int base = blockIdx.x * 64;

    // ---- Phase 1: gather ----
    {
        const int rgrp = tid / TPR;
        const int lanein = tid % TPR;
        const int c4 = lanein * 4;
#pragma unroll
        for (int rr = rgrp; rr < 64; rr += ROWS_PAR) {
            const int row = base + rr;
            float4 acc = make_float4(0.f, 0.f, 0.f, 0.f);
            if (row < nrows) {
                const int beg = __ldg(&rowptr[row]);
                const int end = __ldg(&rowptr[row + 1]);
                int j = beg;
                for (; j + 8 <= end; j += 8) {
                    int2 e[8];
#pragma unroll
                    for (int u = 0; u < 8; u++) e[u] = __ldg(&csr[j + u]);
                    float4 f[8];
#pragma unroll
                    for (int u = 0; u < 8; u++)
                        f[u] = __ldg((const float4*)&feat[(size_t)e[u].x * D + c4]);
#pragma unroll
                    for (int u = 0; u < 8; u++) {
                        float wv = __int_as_float(e[u].y);
                        acc.x += wv * f[u].x;
                        acc.y += wv * f[u].y;
                        acc.z += wv * f[u].z;
                        acc.w += wv * f[u].w;
                    }
                }
                for (; j < end; j++) {
                    int2 e = __ldg(&csr[j]);
                    float wv = __int_as_float(e.y);
                    float4 f = __ldg((const float4*)&feat[(size_t)e.x * D + c4]);
                    acc.x += wv * f.x; acc.y += wv * f.y;
                    acc.z += wv * f.z; acc.w += wv * f.w;
                }
                float sc = rsqrtf(fmaxf((float)__ldg(&indeg[row]), 1.0f));
                acc.x *= sc; acc.y *= sc; acc.z *= sc; acc.w *= sc;
            }
            float* dst = &Ash[rr * ASTRIDE + c4];
            dst[0] = acc.x; dst[1] = acc.y; dst[2] = acc.z; dst[3] = acc.w;
        }
    }

    // ---- Phase 2: TF32 GEMM 64xD @ Dx128 ----
    const int lane = tid & 31;
    const int warp = tid >> 5;      // 0..15
    const int warpM = warp & 3;     // 4 along M: 16 rows each
    const int warpN = warp >> 2;    // 4 along N: 32 cols each

    float acc[4][4];
#pragma unroll
    for (int nt = 0; nt < 4; nt++)
#pragma unroll
        for (int i = 0; i < 4; i++) acc[nt][i] = 0.0f;

    for (int kc = 0; kc < D; kc += 32) {
        __syncthreads();
        // Load W tile 32x128 (convert to tf32); 512 threads x 2 float4 each
#pragma unroll
        for (int it = 0; it < 2; it++) {
            int kk = (tid >> 5) + it * 16;
            int n = (tid & 31) * 4;
            float4 v = *(const float4*)&W[(size_t)(kc + kk) * 128 + n];
            uint32_t* dst = &Wsh[kk * 136 + n];
            dst[0] = f2tf32(v.x); dst[1] = f2tf32(v.y);
            dst[2] = f2tf32(v.z); dst[3] = f2tf32(v.w);
        }
        __syncthreads();

#pragma unroll
        for (int k8 = 0; k8 < 4; k8++) {
            const int kb = k8 * 8;
            const int rA = warpM * 16 + (lane >> 2);
            const int cA = kc + kb + (lane & 3);
            uint32_t afr[4];
            afr[0] = f2tf32(Ash[rA * ASTRIDE + cA]);
            afr[1] = f2tf32(Ash[(rA + 8) * ASTRIDE + cA]);
            afr[2] = f2tf32(Ash[rA * ASTRIDE + cA + 4]);
            afr[3] = f2tf32(Ash[(rA + 8) * ASTRIDE + cA + 4]);
            const int kkB = kb + (lane & 3);
#pragma unroll
            for (int nt = 0; nt < 4; nt++) {
                const int n = warpN * 32 + nt * 8 + (lane >> 2);
                uint32_t b0 = Wsh[kkB * 136 + n];
                uint32_t b1 = Wsh[(kkB + 4) * 136 + n];
                mma_tf32(acc[nt], afr, b0, b1, acc[nt]);
            }
        }
    }

    // ---- Epilogue: bias + relu ----
#pragma unroll
    for (int nt = 0; nt < 4; nt++) {
        int col = warpN * 32 + nt * 8 + (lane & 3) * 2;
        float bb0 = __ldg(&bias[col]);
        float bb1 = __ldg(&bias[col + 1]);
        int r0 = base + warpM * 16 + (lane >> 2);
        if (r0 < nrows) {
            float2 v;
            v.x = fmaxf(acc[nt][0] + bb0, 0.0f);
            v.y = fmaxf(acc[nt][1] + bb1, 0.0f);
            *(float2*)&out[(size_t)r0 * 128 + col] = v;
        }
        int r1 = r0 + 8;
        if (r1 < nrows) {
            float2 v;
            v.x = fmaxf(acc[nt][2] + bb0, 0.0f);
            v.y = fmaxf(acc[nt][3] + bb1, 0.0f);
            *(float2*)&out[(size_t)r1 * 128 + col] = v;
        }
    }
}

// ---------------- launch ----------------
extern "C" void kernel_launch(void* const* d_in, const int* in_sizes, int n_in,
                              void* d_out, int out_size) {
    const float* x    = (const float*)d_in[0];
    const int*   src0 = (const int*)d_in[1];
    const int*   dst0 = (const int*)d_in[2];
    const float* ew0  = (const float*)d_in[3];
    const int*   src1 = (const int*)d_in[4];
    const int*   dst1 = (const int*)d_in[5];
    const float* ew1  = (const float*)d_in[6];
    const float* W1   = (const float*)d_in[7];
    const float* b1   = (const float*)d_in[8];
    const float* W2   = (const float*)d_in[9];
    const float* b2   = (const float*)d_in[10];
    float* out = (float*)d_out;

    int *rowptr0, *indeg0, *rowptr1, *indeg1;
    int *degout0, *degout1;
    int2 *csr0, *csr1;
    float *h1;
    cudaGetSymbolAddress((void**)&rowptr0, g_rowptr0);
    cudaGetSymbolAddress((void**)&csr0,    g_csr0);
    cudaGetSymbolAddress((void**)&indeg0,  g_deg_in0);
    cudaGetSymbolAddress((void**)&degout0, g_deg_out0);
    cudaGetSymbolAddress((void**)&rowptr1, g_rowptr1);
    cudaGetSymbolAddress((void**)&csr1,    g_csr1);
    cudaGetSymbolAddress((void**)&indeg1,  g_deg_in1);
    cudaGetSymbolAddress((void**)&degout1, g_deg_out1);
    cudaGetSymbolAddress((void**)&h1,      g_h1);

    const int smem1 = (64 * (INF + 4)) * 4 + 32 * 136 * 4;   // 83968
    const int smem2 = (64 * (HIDF + 4)) * 4 + 32 * 136 * 4;  // 51200
    cudaFuncSetAttribute(k_fused<INF>,  cudaFuncAttributeMaxDynamicSharedMemorySize, smem1);
    cudaFuncSetAttribute(k_fused<HIDF>, cudaFuncAttributeMaxDynamicSharedMemorySize, smem2);

    // Zero the degree counters via memset nodes (not kernel launches).
    cudaMemsetAsync(degout0, 0, NS0 * sizeof(int), 0);
    cudaMemsetAsync(indeg0,  0, ND0 * sizeof(int), 0);
    cudaMemsetAsync(degout1, 0, NS1 * sizeof(int), 0);
    cudaMemsetAsync(indeg1,  0, ND1 * sizeof(int), 0);

    k_degree<<<(NE0 / 2 + 255) / 256, 256>>>(src0, dst0, src1, dst1);
    k_scan_both<<<2, 1024>>>();
    k_fill<<<(NE0 / 2 + 255) / 256, 256>>>(src0, dst0, ew0, src1, dst1, ew1);
    k_fused<INF><<<(ND0 + 63) / 64, 512, smem1>>>(rowptr0, csr0, x,
                                                  indeg0, W1, b1, h1, ND0);
    k_fused<HIDF><<<(ND1 + 63) / 64, 512, smem2>>>(rowptr1, csr1, h1,
                                                   indeg1, W2, b2, out, ND1);
}

// round 6
// speedup vs baseline: 1.0099x; 1.0099x over previous
#include <cuda_runtime.h>
#include <cuda_bf16.h>
#include <cstdint>

#define NS0 300000
#define ND0 50000
#define NE0 800000
#define NS1 50000
#define ND1 8192
#define NE1 131072
#define INF 256
#define HIDF 128
#define OUTF 128

// ---------------- static device scratch ----------------
// All zero-init counters in ONE contiguous array -> one memset node.
// layout: [deg_out0 | deg_in0 | deg_out1 | deg_in1]
#define OFF_DEGOUT0 0
#define OFF_DEGIN0  (NS0)
#define OFF_DEGOUT1 (NS0 + ND0)
#define OFF_DEGIN1  (NS0 + ND0 + NS1)
#define CNT_TOTAL   (NS0 + ND0 + NS1 + ND1)
__device__ int   g_counters[CNT_TOTAL];

__device__ int   g_rowptr0[ND0 + 1];
__device__ int   g_work0[ND0];        // atomically-bumped rowptr copy
__device__ int2  g_csr0[NE0];         // packed (src, w bits)
__device__ float g_h1[(size_t)ND0 * HIDF];     // 25.6 MB

__device__ int   g_rowptr1[ND1 + 1];
__device__ int   g_work1[ND1];
__device__ int2  g_csr1[NE1];

// ---------------- helpers ----------------
__device__ __forceinline__ uint32_t f2tf32(float f) {
    uint32_t r;
    asm("cvt.rna.tf32.f32 %0, %1;" : "=r"(r) : "f"(f));
    return r;
}

__device__ __forceinline__ void mma_tf32(float d[4], const uint32_t a[4],
                                         const uint32_t b0, const uint32_t b1,
                                         const float c[4]) {
    asm volatile(
        "mma.sync.aligned.m16n8k8.row.col.f32.tf32.tf32.f32 "
        "{%0,%1,%2,%3}, {%4,%5,%6,%7}, {%8,%9}, {%10,%11,%12,%13};\n"
        : "=f"(d[0]), "=f"(d[1]), "=f"(d[2]), "=f"(d[3])
        : "r"(a[0]), "r"(a[1]), "r"(a[2]), "r"(a[3]),
          "r"(b0), "r"(b1),
          "f"(c[0]), "f"(c[1]), "f"(c[2]), "f"(c[3]));
}

// ---------------- preprocessing ----------------

// 2 edges per thread via int2 loads -> 400k threads.
__global__ void __launch_bounds__(256) k_degree(const int* __restrict__ src0,
                                                const int* __restrict__ dst0,
                                                const int* __restrict__ src1,
                                                const int* __restrict__ dst1) {
    int i = blockIdx.x * blockDim.x + threadIdx.x;
    if (i < NE0 / 2) {
        int2 s = ((const int2*)src0)[i];
        int2 d = ((const int2*)dst0)[i];
        atomicAdd(&g_counters[OFF_DEGOUT0 + s.x], 1);
        atomicAdd(&g_counters[OFF_DEGOUT0 + s.y], 1);
        atomicAdd(&g_counters[OFF_DEGIN0 + d.x], 1);
        atomicAdd(&g_counters[OFF_DEGIN0 + d.y], 1);
    }
    if (i < NE1 / 2) {
        int2 s = ((const int2*)src1)[i];
        int2 d = ((const int2*)dst1)[i];
        atomicAdd(&g_counters[OFF_DEGOUT1 + s.x], 1);
        atomicAdd(&g_counters[OFF_DEGOUT1 + s.y], 1);
        atomicAdd(&g_counters[OFF_DEGIN1 + d.x], 1);
        atomicAdd(&g_counters[OFF_DEGIN1 + d.y], 1);
    }
}

// Exclusive scan; writes rowptr AND a working copy for the fill pass.
__device__ __forceinline__ void scan_body(const int* __restrict__ deg,
                                          int* __restrict__ rowptr,
                                          int* __restrict__ work, int n) {
    __shared__ int partial[1024];
    const int t = threadIdx.x;
    const int C = (n + 1023) / 1024;
    const int start = t * C;
    const int end = min(start + C, n);
    int s = 0;
    for (int i = start; i < end; i++) s += deg[i];
    partial[t] = s;
    __syncthreads();
    for (int off = 1; off < 1024; off <<= 1) {
        int v = partial[t];
        int add = (t >= off) ? partial[t - off] : 0;
        __syncthreads();
        partial[t] = v + add;
        __syncthreads();
    }
    int run = (t == 0) ? 0 : partial[t - 1];
    for (int i = start; i < end; i++) {
        rowptr[i] = run;
        work[i] = run;
        run += deg[i];
    }
    if (t == 0) rowptr[n] = partial[1023];
}

__global__ void k_scan_both() {
    if (blockIdx.x == 0) scan_body(&g_counters[OFF_DEGIN0], g_rowptr0, g_work0, ND0);
    else                 scan_body(&g_counters[OFF_DEGIN1], g_rowptr1, g_work1, ND1);
}

// 2 edges per thread; atomic bump on the rowptr working copy; packed store.
__global__ void __launch_bounds__(256) k_fill(const int* __restrict__ src0,
                                              const int* __restrict__ dst0,
                                              const float* __restrict__ ew0,
                                              const int* __restrict__ src1,
                                              const int* __restrict__ dst1,
                                              const float* __restrict__ ew1) {
    int i = blockIdx.x * blockDim.x + threadIdx.x;
    if (i < NE0 / 2) {
        int2   s = ((const int2*)src0)[i];
        int2   d = ((const int2*)dst0)[i];
        float2 w = ((const float2*)ew0)[i];
        int pos0 = atomicAdd(&g_work0[d.x], 1);
        int pos1 = atomicAdd(&g_work0[d.y], 1);
        float w0 = w.x * rsqrtf(fmaxf((float)g_counters[OFF_DEGOUT0 + s.x], 1.0f));
        float w1 = w.y * rsqrtf(fmaxf((float)g_counters[OFF_DEGOUT0 + s.y], 1.0f));
        g_csr0[pos0] = make_int2(s.x, __float_as_int(w0));
        g_csr0[pos1] = make_int2(s.y, __float_as_int(w1));
    }
    if (i < NE1 / 2) {
        int2   s = ((const int2*)src1)[i];
        int2   d = ((const int2*)dst1)[i];
        float2 w = ((const float2*)ew1)[i];
        int pos0 = atomicAdd(&g_work1[d.x], 1);
        int pos1 = atomicAdd(&g_work1[d.y], 1);
        float w0 = w.x * rsqrtf(fmaxf((float)g_counters[OFF_DEGOUT1 + s.x], 1.0f));
        float w1 = w.y * rsqrtf(fmaxf((float)g_counters[OFF_DEGOUT1 + s.y], 1.0f));
        g_csr1[pos0] = make_int2(s.x, __float_as_int(w0));
        g_csr1[pos1] = make_int2(s.y, __float_as_int(w1));
    }
}

// ---------------- fused aggregate + TF32 GEMM ----------------
// Per block (512 threads): gather 32 dst rows (D feats each) into smem,
// then compute relu(A[32,D] @ W[D,128] + bias) with tensor cores.
// Smem ~50.7 KB (D=256) -> 3 blocks/SM (reg-limited), 75% occupancy.
// 16 warps: 2 along M (16 rows each) x 8 along N (16 cols each).
template <int D>
__global__ void __launch_bounds__(512) k_fused(const int* __restrict__ rowptr,
                                               const int2* __restrict__ csr,
                                               const float* __restrict__ feat,
                                               const int* __restrict__ indeg,
                                               const float* __restrict__ W,
                                               const float* __restrict__ bias,
                                               float* __restrict__ out,
                                               int nrows) {
    constexpr int ASTRIDE = D + 4;
    constexpr int TPR = D / 4;           // threads per row (float4 each)
    constexpr int ROWS_PAR = 512 / TPR;  // rows gathered in parallel
    extern __shared__ char smem_raw[];
    float*    Ash = (float*)smem_raw;                          // 32*ASTRIDE floats
    uint32_t* Wsh = (uint32_t*)(smem_raw + 32 * ASTRIDE * 4);  // 32*136 u32

    const int tid = threadIdx.x;
    const int base = blockIdx.x * 32;

    // ---- Phase 1: gather ----
    {
        const int rgrp = tid / TPR;
        const int lanein = tid % TPR;
        const int c4 = lanein * 4;
#pragma unroll
        for (int rr = rgrp; rr < 32; rr += ROWS_PAR) {
            const int row = base + rr;
            float4 acc = make_float4(0.f, 0.f, 0.f, 0.f);
            if (row < nrows) {
                const int beg = __ldg(&rowptr[row]);
                const int end = __ldg(&rowptr[row + 1]);
                int j = beg;
                for (; j + 8 <= end; j += 8) {
                    int2 e[8];
#pragma unroll
                    for (int u = 0; u < 8; u++) e[u] = __ldg(&csr[j + u]);
                    float4 f[8];
#pragma unroll
                    for (int u = 0; u < 8; u++)
                        f[u] = __ldg((const float4*)&feat[(size_t)e[u].x * D + c4]);
#pragma unroll
                    for (int u = 0; u < 8; u++) {
                        float wv = __int_as_float(e[u].y);
                        acc.x += wv * f[u].x;
                        acc.y += wv * f[u].y;
                        acc.z += wv * f[u].z;
                        acc.w += wv * f[u].w;
                    }
                }
                for (; j < end; j++) {
                    int2 e = __ldg(&csr[j]);
                    float wv = __int_as_float(e.y);
                    float4 f = __ldg((const float4*)&feat[(size_t)e.x * D + c4]);
                    acc.x += wv * f.x; acc.y += wv * f.y;
                    acc.z += wv * f.z; acc.w += wv * f.w;
                }
                float sc = rsqrtf(fmaxf((float)__ldg(&indeg[row]), 1.0f));
                acc.x *= sc; acc.y *= sc; acc.z *= sc; acc.w *= sc;
            }
            float* dst = &Ash[rr * ASTRIDE + c4];
            dst[0] = acc.x; dst[1] = acc.y; dst[2] = acc.z; dst[3] = acc.w;
        }
    }

    // ---- Phase 2: TF32 GEMM 32xD @ Dx128 ----
    const int lane = tid & 31;
    const int warp = tid >> 5;      // 0..15
    const int warpM = warp & 1;     // 2 along M: 16 rows each
    const int warpN = warp >> 1;    // 8 along N: 16 cols each

    float acc[2][4];
#pragma unroll
    for (int nt = 0; nt < 2; nt++)
#pragma unroll
        for (int i = 0; i < 4; i++) acc[nt][i] = 0.0f;

    for (int kc = 0; kc < D; kc += 32) {
        __syncthreads();
        // Load W tile 32x128 (convert to tf32); 512 threads x 2 float4 each
#pragma unroll
        for (int it = 0; it < 2; it++) {
            int kk = (tid >> 5) + it * 16;
            int n = (tid & 31) * 4;
            float4 v = *(const float4*)&W[(size_t)(kc + kk) * 128 + n];
            uint32_t* dst = &Wsh[kk * 136 + n];
            dst[0] = f2tf32(v.x); dst[1] = f2tf32(v.y);
            dst[2] = f2tf32(v.z); dst[3] = f2tf32(v.w);
        }
        __syncthreads();

#pragma unroll
        for (int k8 = 0; k8 < 4; k8++) {
            const int kb = k8 * 8;
            const int rA = warpM * 16 + (lane >> 2);
            const int cA = kc + kb + (lane & 3);
            uint32_t afr[4];
            afr[0] = f2tf32(Ash[rA * ASTRIDE + cA]);
            afr[1] = f2tf32(Ash[(rA + 8) * ASTRIDE + cA]);
            afr[2] = f2tf32(Ash[rA * ASTRIDE + cA + 4]);
            afr[3] = f2tf32(Ash[(rA + 8) * ASTRIDE + cA + 4]);
            const int kkB = kb + (lane & 3);
#pragma unroll
            for (int nt = 0; nt < 2; nt++) {
                const int n = warpN * 16 + nt * 8 + (lane >> 2);
                uint32_t b0 = Wsh[kkB * 136 + n];
                uint32_t b1 = Wsh[(kkB + 4) * 136 + n];
                mma_tf32(acc[nt], afr, b0, b1, acc[nt]);
            }
        }
    }

    // ---- Epilogue: bias + relu ----
#pragma unroll
    for (int nt = 0; nt < 2; nt++) {
        int col = warpN * 16 + nt * 8 + (lane & 3) * 2;
        float bb0 = __ldg(&bias[col]);
        float bb1 = __ldg(&bias[col + 1]);
        int r0 = base + warpM * 16 + (lane >> 2);
        if (r0 < nrows) {
            float2 v;
            v.x = fmaxf(acc[nt][0] + bb0, 0.0f);
            v.y = fmaxf(acc[nt][1] + bb1, 0.0f);
            *(float2*)&out[(size_t)r0 * 128 + col] = v;
        }
        int r1 = r0 + 8;
        if (r1 < nrows) {
            float2 v;
            v.x = fmaxf(acc[nt][2] + bb0, 0.0f);
            v.y = fmaxf(acc[nt][3] + bb1, 0.0f);
            *(float2*)&out[(size_t)r1 * 128 + col] = v;
        }
    }
}

// ---------------- launch ----------------
extern "C" void kernel_launch(void* const* d_in, const int* in_sizes, int n_in,
                              void* d_out, int out_size) {
    const float* x    = (const float*)d_in[0];
    const int*   src0 = (const int*)d_in[1];
    const int*   dst0 = (const int*)d_in[2];
    const float* ew0  = (const float*)d_in[3];
    const int*   src1 = (const int*)d_in[4];
    const int*   dst1 = (const int*)d_in[5];
    const float* ew1  = (const float*)d_in[6];
    const float* W1   = (const float*)d_in[7];
    const float* b1   = (const float*)d_in[8];
    const float* W2   = (const float*)d_in[9];
    const float* b2   = (const float*)d_in[10];
    float* out = (float*)d_out;

    int *counters, *rowptr0, *rowptr1;
    int2 *csr0, *csr1;
    float *h1;
    cudaGetSymbolAddress((void**)&counters, g_counters);
    cudaGetSymbolAddress((void**)&rowptr0,  g_rowptr0);
    cudaGetSymbolAddress((void**)&csr0,     g_csr0);
    cudaGetSymbolAddress((void**)&rowptr1,  g_rowptr1);
    cudaGetSymbolAddress((void**)&csr1,     g_csr1);
    cudaGetSymbolAddress((void**)&h1,       g_h1);

    const int* indeg0 = counters + OFF_DEGIN0;
    const int* indeg1 = counters + OFF_DEGIN1;

    const int smem1 = (32 * (INF + 4)) * 4 + 32 * 136 * 4;   // 50688
    const int smem2 = (32 * (HIDF + 4)) * 4 + 32 * 136 * 4;  // 34304
    cudaFuncSetAttribute(k_fused<INF>,  cudaFuncAttributeMaxDynamicSharedMemorySize, smem1);
    cudaFuncSetAttribute(k_fused<HIDF>, cudaFuncAttributeMaxDynamicSharedMemorySize, smem2);

    // ONE memset node for all counters.
    cudaMemsetAsync(counters, 0, CNT_TOTAL * sizeof(int), 0);

    k_degree<<<(NE0 / 2 + 255) / 256, 256>>>(src0, dst0, src1, dst1);
    k_scan_both<<<2, 1024>>>();
    k_fill<<<(NE0 / 2 + 255) / 256, 256>>>(src0, dst0, ew0, src1, dst1, ew1);
    k_fused<INF><<<(ND0 + 31) / 32, 512, smem1>>>(rowptr0, csr0, x,
                                                  indeg0, W1, b1, h1, ND0);
    k_fused<HIDF><<<(ND1 + 31) / 32, 512, smem2>>>(rowptr1, csr1, h1,
                                                   indeg1, W2, b2, out, ND1);
}